// round 1
// baseline (speedup 1.0000x reference)
#include <cuda_runtime.h>
#include <math.h>

#define B_   4
#define S_   4096
#define D_   1024
#define ROWS (B_ * S_)        // 16384
#define NSEG 32
#define SEGLEN (S_ / NSEG)    // 128

// ---------------- scratch (static device globals; no allocations) -------------
__device__ float sc_h [(size_t)ROWS * D_];       // LN1 output
__device__ float sc_g [(size_t)ROWS * D_];       // sigmoid gate
__device__ float sc_v [(size_t)ROWS * D_];       // value
__device__ float sc_x [(size_t)ROWS * D_];       // x after memory residual
__device__ float sc_h2[(size_t)ROWS * D_];       // LN2 output
__device__ float sc_u [(size_t)ROWS * 4 * D_];   // gelu(h2 @ W1 + b1)
__device__ float sc_pg [(size_t)B_ * NSEG * D_]; // segment partial sums of g
__device__ float sc_pgv[(size_t)B_ * NSEG * D_]; // segment partial sums of g*v

// ---------------- LayerNorm: one CTA per row, 256 threads, float4 -------------
__global__ __launch_bounds__(256) void ln_kernel(
    const float* __restrict__ x, const float* __restrict__ gamma,
    const float* __restrict__ beta, float* __restrict__ out)
{
    int row = blockIdx.x;
    int tid = threadIdx.x;
    const float4* xr = (const float4*)(x + (size_t)row * D_);
    float4 v = xr[tid];

    float s  = v.x + v.y + v.z + v.w;
    float sq = v.x*v.x + v.y*v.y + v.z*v.z + v.w*v.w;

    __shared__ float red0[8], red1[8];
    #pragma unroll
    for (int o = 16; o > 0; o >>= 1) {
        s  += __shfl_xor_sync(0xffffffffu, s,  o);
        sq += __shfl_xor_sync(0xffffffffu, sq, o);
    }
    if ((tid & 31) == 0) { red0[tid >> 5] = s; red1[tid >> 5] = sq; }
    __syncthreads();
    if (tid < 32) {
        s  = (tid < 8) ? red0[tid] : 0.f;
        sq = (tid < 8) ? red1[tid] : 0.f;
        #pragma unroll
        for (int o = 4; o > 0; o >>= 1) {
            s  += __shfl_xor_sync(0xffffffffu, s,  o);
            sq += __shfl_xor_sync(0xffffffffu, sq, o);
        }
        if (tid == 0) {
            float mu = s * (1.0f / D_);
            float var = sq * (1.0f / D_) - mu * mu;
            red0[0] = mu;
            red1[0] = rsqrtf(var + 1e-5f);
        }
    }
    __syncthreads();
    float mu = red0[0], rstd = red1[0];

    float4 gv = ((const float4*)gamma)[tid];
    float4 bv = ((const float4*)beta)[tid];
    float4 o;
    o.x = (v.x - mu) * rstd * gv.x + bv.x;
    o.y = (v.y - mu) * rstd * gv.y + bv.y;
    o.z = (v.z - mu) * rstd * gv.z + bv.z;
    o.w = (v.w - mu) * rstd * gv.w + bv.w;
    ((float4*)(out + (size_t)row * D_))[tid] = o;
}

// ---------------- SGEMM: C = A[M,K] @ B[K,N] (+bias, epilogue) -----------------
// 128x128 block, BK=8, 256 threads, 8x8 per thread.
enum { EPI_NONE = 0, EPI_SIGMOID = 1, EPI_GELU = 2, EPI_ADD = 3 };

template <int EPI>
__global__ __launch_bounds__(256) void sgemm_kernel(
    const float* __restrict__ A, const float* __restrict__ Bm,
    const float* __restrict__ bias, const float* __restrict__ addsrc,
    float* __restrict__ C, int M, int N, int K)
{
    const int BM = 128, BN = 128, BK = 8;
    __shared__ float As[BK][BM];
    __shared__ float Bs[BK][BN];

    int tid  = threadIdx.x;
    int row0 = blockIdx.y * BM;
    int col0 = blockIdx.x * BN;
    int tx = tid & 15;       // 0..15 -> 8 cols each
    int ty = tid >> 4;       // 0..15 -> 8 rows each

    float acc[8][8];
    #pragma unroll
    for (int i = 0; i < 8; i++)
        #pragma unroll
        for (int j = 0; j < 8; j++) acc[i][j] = 0.f;

    int arow = tid >> 1;          // 0..127
    int acol = (tid & 1) * 4;     // 0 or 4
    int brow = tid >> 5;          // 0..7
    int bcol = (tid & 31) * 4;    // 0..124

    const float* Aptr = A  + (size_t)(row0 + arow) * K + acol;
    const float* Bptr = Bm + (size_t)brow * N + col0 + bcol;

    for (int k0 = 0; k0 < K; k0 += BK) {
        float4 av = *(const float4*)(Aptr + k0);
        float4 bv = *(const float4*)(Bptr + (size_t)k0 * N);
        As[acol + 0][arow] = av.x;
        As[acol + 1][arow] = av.y;
        As[acol + 2][arow] = av.z;
        As[acol + 3][arow] = av.w;
        *(float4*)&Bs[brow][bcol] = bv;
        __syncthreads();

        #pragma unroll
        for (int k = 0; k < BK; k++) {
            float ra[8], rb[8];
            #pragma unroll
            for (int i = 0; i < 8; i++) ra[i] = As[k][ty * 8 + i];
            #pragma unroll
            for (int j = 0; j < 8; j++) rb[j] = Bs[k][tx * 8 + j];
            #pragma unroll
            for (int i = 0; i < 8; i++)
                #pragma unroll
                for (int j = 0; j < 8; j++)
                    acc[i][j] += ra[i] * rb[j];
        }
        __syncthreads();
    }

    // epilogue
    #pragma unroll
    for (int i = 0; i < 8; i++) {
        int r = row0 + ty * 8 + i;
        size_t rbase = (size_t)r * N + col0 + tx * 8;
        #pragma unroll
        for (int j = 0; j < 8; j++) {
            float val = acc[i][j] + bias[col0 + tx * 8 + j];
            if (EPI == EPI_SIGMOID) {
                val = 1.0f / (1.0f + expf(-val));
            } else if (EPI == EPI_GELU) {
                val = 0.5f * val * (1.0f + erff(val * 0.70710678118654752f));
            } else if (EPI == EPI_ADD) {
                val += addsrc[rbase + j];
            }
            C[rbase + j] = val;
        }
    }
}

// ---------------- cumsum over sequence axis (3 passes) -------------------------
// Pass A: per-segment sums of g and g*v.
__global__ __launch_bounds__(256) void cums_partial(
    const float* __restrict__ g, const float* __restrict__ v,
    float* __restrict__ pg, float* __restrict__ pgv)
{
    int bs  = blockIdx.x;            // b*NSEG + seg
    int b   = bs / NSEG;
    int seg = bs % NSEG;
    int d   = blockIdx.y * 256 + threadIdx.x;
    size_t base = ((size_t)b * S_ + (size_t)seg * SEGLEN) * D_ + d;

    float sg = 0.f, sgv = 0.f;
    #pragma unroll 4
    for (int s = 0; s < SEGLEN; s++) {
        float gg = g[base + (size_t)s * D_];
        float vv = v[base + (size_t)s * D_];
        sg  += gg;
        sgv += gg * vv;
    }
    size_t o = ((size_t)b * NSEG + seg) * D_ + d;
    pg[o]  = sg;
    pgv[o] = sgv;
}

// Pass B: in-place exclusive scan over NSEG segments per (b,d).
__global__ __launch_bounds__(256) void cums_scan(
    float* __restrict__ pg, float* __restrict__ pgv)
{
    int idx = blockIdx.x * 256 + threadIdx.x;  // 0 .. B_*D_-1
    int b = idx / D_;
    int d = idx % D_;
    float rg = 0.f, rgv = 0.f;
    for (int seg = 0; seg < NSEG; seg++) {
        size_t o = ((size_t)b * NSEG + seg) * D_ + d;
        float tg = pg[o], tgv = pgv[o];
        pg[o]  = rg;
        pgv[o] = rgv;
        rg  += tg;
        rgv += tgv;
    }
}

// Pass C: inclusive running sums within segment + residual write.
__global__ __launch_bounds__(256) void cums_apply(
    const float* __restrict__ g, const float* __restrict__ v,
    const float* __restrict__ x,
    const float* __restrict__ pg, const float* __restrict__ pgv,
    float* __restrict__ xout)
{
    int bs  = blockIdx.x;
    int b   = bs / NSEG;
    int seg = bs % NSEG;
    int d   = blockIdx.y * 256 + threadIdx.x;
    size_t base = ((size_t)b * S_ + (size_t)seg * SEGLEN) * D_ + d;
    size_t po   = ((size_t)b * NSEG + seg) * D_ + d;

    float rg  = pg[po];
    float rgv = pgv[po];
    for (int s = 0; s < SEGLEN; s++) {
        size_t o = base + (size_t)s * D_;
        float gg = g[o];
        float vv = v[o];
        rgv += gg * vv;
        rg  += gg;
        xout[o] = x[o] + rgv / (rg + 1e-6f);
    }
}

// ---------------- launch --------------------------------------------------------
extern "C" void kernel_launch(void* const* d_in, const int* in_sizes, int n_in,
                              void* d_out, int out_size)
{
    const float* x       = (const float*)d_in[0];
    const float* ln1_g   = (const float*)d_in[1];
    const float* ln1_b   = (const float*)d_in[2];
    const float* ln2_g   = (const float*)d_in[3];
    const float* ln2_b   = (const float*)d_in[4];
    const float* gate_w  = (const float*)d_in[5];
    const float* gate_b  = (const float*)d_in[6];
    const float* value_w = (const float*)d_in[7];
    const float* value_b = (const float*)d_in[8];
    const float* ffn_w1  = (const float*)d_in[9];
    const float* ffn_b1  = (const float*)d_in[10];
    const float* ffn_w2  = (const float*)d_in[11];
    const float* ffn_b2  = (const float*)d_in[12];
    float* out = (float*)d_out;

    float *h, *g, *v, *xn, *h2, *u, *pg, *pgv;
    cudaGetSymbolAddress((void**)&h,   sc_h);
    cudaGetSymbolAddress((void**)&g,   sc_g);
    cudaGetSymbolAddress((void**)&v,   sc_v);
    cudaGetSymbolAddress((void**)&xn,  sc_x);
    cudaGetSymbolAddress((void**)&h2,  sc_h2);
    cudaGetSymbolAddress((void**)&u,   sc_u);
    cudaGetSymbolAddress((void**)&pg,  sc_pg);
    cudaGetSymbolAddress((void**)&pgv, sc_pgv);

    // 1. h = LN1(x)
    ln_kernel<<<ROWS, 256>>>(x, ln1_g, ln1_b, h);

    // 2/3. gate + value GEMMs (D x D)
    dim3 gridDD(D_ / 128, ROWS / 128);
    sgemm_kernel<EPI_SIGMOID><<<gridDD, 256>>>(h, gate_w, gate_b, nullptr, g,
                                               ROWS, D_, D_);
    sgemm_kernel<EPI_NONE><<<gridDD, 256>>>(h, value_w, value_b, nullptr, v,
                                            ROWS, D_, D_);

    // 4. memory residual: x_new = x + cumsum(g*v)/(cumsum(g)+eps)
    dim3 gridCum(B_ * NSEG, D_ / 256);
    cums_partial<<<gridCum, 256>>>(g, v, pg, pgv);
    cums_scan<<<(B_ * D_) / 256, 256>>>(pg, pgv);
    cums_apply<<<gridCum, 256>>>(g, v, x, pg, pgv, xn);

    // 5. h2 = LN2(x_new)
    ln_kernel<<<ROWS, 256>>>(xn, ln2_g, ln2_b, h2);

    // 6. u = gelu(h2 @ W1 + b1)   (D -> 4D)
    dim3 gridFF1(4 * D_ / 128, ROWS / 128);
    sgemm_kernel<EPI_GELU><<<gridFF1, 256>>>(h2, ffn_w1, ffn_b1, nullptr, u,
                                             ROWS, 4 * D_, D_);

    // 7. out = x_new + u @ W2 + b2   (4D -> D)
    sgemm_kernel<EPI_ADD><<<gridDD, 256>>>(u, ffn_w2, ffn_b2, xn, out,
                                           ROWS, D_, 4 * D_);
}

// round 3
// speedup vs baseline: 4.0712x; 4.0712x over previous
#include <cuda_runtime.h>
#include <math.h>
#include <stdint.h>

#define B_   4
#define S_   4096
#define D_   1024
#define ROWS (B_ * S_)        // 16384
#define NSEG 32
#define SEGLEN (S_ / NSEG)    // 128

// ---------------- scratch (static device globals; no allocations) -------------
__device__ float sc_h [(size_t)ROWS * D_];
__device__ float sc_g [(size_t)ROWS * D_];
__device__ float sc_v [(size_t)ROWS * D_];
__device__ float sc_x [(size_t)ROWS * D_];
__device__ float sc_h2[(size_t)ROWS * D_];
__device__ float sc_u [(size_t)ROWS * 4 * D_];
__device__ float sc_pg [(size_t)B_ * NSEG * D_];
__device__ float sc_pgv[(size_t)B_ * NSEG * D_];
__device__ float sc_gwt[(size_t)D_ * D_];        // gate_w^T  [N,K]
__device__ float sc_vwt[(size_t)D_ * D_];        // value_w^T [N,K]
__device__ float sc_w1t[(size_t)4 * D_ * D_];    // ffn_w1^T  [4D, D]
__device__ float sc_w2t[(size_t)D_ * 4 * D_];    // ffn_w2^T  [D, 4D]

// =================== helpers ====================================================
__device__ __forceinline__ uint32_t smem_u32(const void* p) {
    uint32_t a;
    asm("{ .reg .u64 t; cvta.to.shared.u64 t, %1; cvt.u32.u64 %0, t; }"
        : "=r"(a) : "l"(p));
    return a;
}

// round-to-nearest tf32 (unbiased; applied once at producers)
__device__ __forceinline__ float tf32r(float x) {
    uint32_t u;
    asm("cvt.rna.tf32.f32 %0, %1;" : "=r"(u) : "f"(x));
    return __uint_as_float(u);
}

#define CP_COMMIT() asm volatile("cp.async.commit_group;" ::: "memory")
template <int N> __device__ __forceinline__ void cp_wait() {
    asm volatile("cp.async.wait_group %0;" :: "n"(N) : "memory");
}
__device__ __forceinline__ void cpasync16(uint32_t saddr, const void* g) {
    asm volatile("cp.async.cg.shared.global [%0], [%1], 16;"
                 :: "r"(saddr), "l"(g) : "memory");
}

__device__ __forceinline__ void mma_tf32(float* c, const uint32_t* a, const uint32_t* b) {
    asm volatile(
        "mma.sync.aligned.m16n8k8.row.col.f32.tf32.tf32.f32 "
        "{%0,%1,%2,%3}, {%4,%5,%6,%7}, {%8,%9}, {%0,%1,%2,%3};"
        : "+f"(c[0]), "+f"(c[1]), "+f"(c[2]), "+f"(c[3])
        : "r"(a[0]), "r"(a[1]), "r"(a[2]), "r"(a[3]), "r"(b[0]), "r"(b[1]));
}

// =================== mma.sync TF32 GEMM =========================================
// C[M,N] = A[M,K] @ Bt[N,K]^T (+bias, epilogue). A, Bt pre-rounded to tf32.
enum { EPI_NONE = 0, EPI_SIGMOID = 1, EPI_GELU = 2, EPI_ADD = 3 };

#define TILE_F   4096            // 128 rows * 32 floats (16KB), XOR-swizzled
#define STAGE_F  (2 * TILE_F)    // A + B per stage
#define NSTG     3
#define GEMM_SMEM (NSTG * STAGE_F * 4)   // 98304 bytes

template <int EPI>
__global__ __launch_bounds__(256, 2) void gemm_mma(
    const float* __restrict__ A, const float* __restrict__ Bt,
    const float* __restrict__ bias, const float* __restrict__ addsrc,
    float* __restrict__ C, int M, int N, int K)
{
    extern __shared__ float sm[];
    uint32_t smb = smem_u32(sm);

    int tid  = threadIdx.x;
    int warp = tid >> 5, lane = tid & 31;
    int g = lane >> 2, t = lane & 3;
    int wm = warp >> 1, wn = warp & 1;          // 4 x 2 warp grid
    int row0 = blockIdx.y * 128;
    int col0 = blockIdx.x * 128;
    int KCH  = K >> 5;

    // ---- load mapping: thread covers rows lr+32i, 16B chunk lc, XOR swizzle ----
    int lr = tid >> 3;          // 0..31
    int lc = tid & 7;           // 0..7
    uint32_t st_off[4];
    #pragma unroll
    for (int i = 0; i < 4; i++) {
        int row = lr + 32 * i;
        st_off[i] = (uint32_t)(row * 128 + ((lc ^ (row & 7)) << 4));
    }
    const float* gA = A  + (size_t)(row0 + lr) * K + lc * 4;
    const float* gB = Bt + (size_t)(col0 + lr) * K + lc * 4;

    float c[2][8][4];
    #pragma unroll
    for (int i = 0; i < 2; i++)
        #pragma unroll
        for (int j = 0; j < 8; j++)
            #pragma unroll
            for (int q = 0; q < 4; q++) c[i][j][q] = 0.f;

    // prologue: stages 0,1
    #pragma unroll
    for (int s = 0; s < 2; s++) {
        uint32_t ab = smb + s * (STAGE_F * 4);
        uint32_t bb = ab + TILE_F * 4;
        #pragma unroll
        for (int i = 0; i < 4; i++) {
            cpasync16(ab + st_off[i], gA + (size_t)i * 32 * K + s * 32);
            cpasync16(bb + st_off[i], gB + (size_t)i * 32 * K + s * 32);
        }
        CP_COMMIT();
    }

    int rm0 = wm * 32 + g;      // mtile 0 row (low)
    int cn0 = wn * 64 + g;      // ntile 0 col base

    for (int kc = 0; kc < KCH; kc++) {
        __syncthreads();        // all warps done with buffer (kc-1)%3
        if (kc + 2 < KCH) {
            int s2 = (kc + 2) % NSTG;
            uint32_t ab = smb + s2 * (STAGE_F * 4);
            uint32_t bb = ab + TILE_F * 4;
            #pragma unroll
            for (int i = 0; i < 4; i++) {
                cpasync16(ab + st_off[i], gA + (size_t)i * 32 * K + (kc + 2) * 32);
                cpasync16(bb + st_off[i], gB + (size_t)i * 32 * K + (kc + 2) * 32);
            }
        }
        CP_COMMIT();
        cp_wait<2>();
        __syncthreads();        // stage kc visible to all

        const float* sA = sm + (kc % NSTG) * STAGE_F;
        const float* sB = sA + TILE_F;

        #pragma unroll
        for (int ks = 0; ks < 4; ks++) {
            int ch0 = ks * 2, ch1 = ks * 2 + 1;
            int sw0 = ((ch0 ^ g) << 2) + t;
            int sw1 = ((ch1 ^ g) << 2) + t;

            uint32_t a[2][4];
            #pragma unroll
            for (int i = 0; i < 2; i++) {
                int r = rm0 + i * 16;
                a[i][0] = __float_as_uint(sA[r * 32 + sw0]);
                a[i][1] = __float_as_uint(sA[(r + 8) * 32 + sw0]);
                a[i][2] = __float_as_uint(sA[r * 32 + sw1]);
                a[i][3] = __float_as_uint(sA[(r + 8) * 32 + sw1]);
            }
            uint32_t b[8][2];
            #pragma unroll
            for (int j = 0; j < 8; j++) {
                int n = cn0 + j * 8;
                b[j][0] = __float_as_uint(sB[n * 32 + sw0]);
                b[j][1] = __float_as_uint(sB[n * 32 + sw1]);
            }
            #pragma unroll
            for (int i = 0; i < 2; i++)
                #pragma unroll
                for (int j = 0; j < 8; j++)
                    mma_tf32(c[i][j], a[i], b[j]);
        }
    }

    // ---- epilogue: per (i,j): rows rm0+i*16 (+8), cols cn0-g + j*8 + 2t --------
    #pragma unroll
    for (int i = 0; i < 2; i++) {
        int rlo = row0 + wm * 32 + i * 16 + g;
        #pragma unroll
        for (int j = 0; j < 8; j++) {
            int col = col0 + wn * 64 + j * 8 + 2 * t;
            float2 bv = *(const float2*)(bias + col);
            float2 lo, hi;
            lo.x = c[i][j][0] + bv.x;  lo.y = c[i][j][1] + bv.y;
            hi.x = c[i][j][2] + bv.x;  hi.y = c[i][j][3] + bv.y;
            size_t olo = (size_t)rlo * N + col;
            size_t ohi = olo + (size_t)8 * N;
            if (EPI == EPI_SIGMOID) {
                lo.x = 1.f / (1.f + __expf(-lo.x)); lo.y = 1.f / (1.f + __expf(-lo.y));
                hi.x = 1.f / (1.f + __expf(-hi.x)); hi.y = 1.f / (1.f + __expf(-hi.y));
            } else if (EPI == EPI_GELU) {
                lo.x = tf32r(0.5f * lo.x * (1.f + erff(lo.x * 0.70710678118654752f)));
                lo.y = tf32r(0.5f * lo.y * (1.f + erff(lo.y * 0.70710678118654752f)));
                hi.x = tf32r(0.5f * hi.x * (1.f + erff(hi.x * 0.70710678118654752f)));
                hi.y = tf32r(0.5f * hi.y * (1.f + erff(hi.y * 0.70710678118654752f)));
            } else if (EPI == EPI_ADD) {
                float2 a0 = *(const float2*)(addsrc + olo);
                float2 a1 = *(const float2*)(addsrc + ohi);
                lo.x += a0.x; lo.y += a0.y; hi.x += a1.x; hi.y += a1.y;
            }
            *(float2*)(C + olo) = lo;
            *(float2*)(C + ohi) = hi;
        }
    }
}

// =================== transpose (rounds to tf32): in[R,C] -> out[C,R] ===========
__global__ __launch_bounds__(256) void transpose_kernel(
    const float* __restrict__ in, float* __restrict__ out, int R, int C)
{
    __shared__ float t[32][33];
    int bx = blockIdx.x * 32, by = blockIdx.y * 32;
    int tx = threadIdx.x & 31, ty = threadIdx.x >> 5;
    #pragma unroll
    for (int i = 0; i < 32; i += 8)
        t[ty + i][tx] = in[(size_t)(by + ty + i) * C + bx + tx];
    __syncthreads();
    #pragma unroll
    for (int i = 0; i < 32; i += 8)
        out[(size_t)(bx + ty + i) * R + by + tx] = tf32r(t[tx][ty + i]);
}

// =================== LayerNorm (rounds output to tf32) ========================
__global__ __launch_bounds__(256) void ln_kernel(
    const float* __restrict__ x, const float* __restrict__ gamma,
    const float* __restrict__ beta, float* __restrict__ out)
{
    int row = blockIdx.x;
    int tid = threadIdx.x;
    const float4* xr = (const float4*)(x + (size_t)row * D_);
    float4 v = xr[tid];

    float s  = v.x + v.y + v.z + v.w;
    float sq = v.x*v.x + v.y*v.y + v.z*v.z + v.w*v.w;

    __shared__ float red0[8], red1[8];
    #pragma unroll
    for (int o = 16; o > 0; o >>= 1) {
        s  += __shfl_xor_sync(0xffffffffu, s,  o);
        sq += __shfl_xor_sync(0xffffffffu, sq, o);
    }
    if ((tid & 31) == 0) { red0[tid >> 5] = s; red1[tid >> 5] = sq; }
    __syncthreads();
    if (tid < 32) {
        s  = (tid < 8) ? red0[tid] : 0.f;
        sq = (tid < 8) ? red1[tid] : 0.f;
        #pragma unroll
        for (int o = 4; o > 0; o >>= 1) {
            s  += __shfl_xor_sync(0xffffffffu, s,  o);
            sq += __shfl_xor_sync(0xffffffffu, sq, o);
        }
        if (tid == 0) {
            float mu = s * (1.0f / D_);
            float var = sq * (1.0f / D_) - mu * mu;
            red0[0] = mu;
            red1[0] = rsqrtf(var + 1e-5f);
        }
    }
    __syncthreads();
    float mu = red0[0], rstd = red1[0];

    float4 gv = ((const float4*)gamma)[tid];
    float4 bv = ((const float4*)beta)[tid];
    float4 o;
    o.x = tf32r((v.x - mu) * rstd * gv.x + bv.x);
    o.y = tf32r((v.y - mu) * rstd * gv.y + bv.y);
    o.z = tf32r((v.z - mu) * rstd * gv.z + bv.z);
    o.w = tf32r((v.w - mu) * rstd * gv.w + bv.w);
    ((float4*)(out + (size_t)row * D_))[tid] = o;
}

// =================== cumsum over sequence axis (3 passes) =====================
__global__ __launch_bounds__(256) void cums_partial(
    const float* __restrict__ g, const float* __restrict__ v,
    float* __restrict__ pg, float* __restrict__ pgv)
{
    int bs  = blockIdx.x;
    int b   = bs / NSEG;
    int seg = bs % NSEG;
    int d   = blockIdx.y * 256 + threadIdx.x;
    size_t base = ((size_t)b * S_ + (size_t)seg * SEGLEN) * D_ + d;

    float sg = 0.f, sgv = 0.f;
    #pragma unroll 4
    for (int s = 0; s < SEGLEN; s++) {
        float gg = g[base + (size_t)s * D_];
        float vv = v[base + (size_t)s * D_];
        sg  += gg;
        sgv += gg * vv;
    }
    size_t o = ((size_t)b * NSEG + seg) * D_ + d;
    pg[o]  = sg;
    pgv[o] = sgv;
}

__global__ __launch_bounds__(256) void cums_scan(
    float* __restrict__ pg, float* __restrict__ pgv)
{
    int idx = blockIdx.x * 256 + threadIdx.x;
    int b = idx / D_;
    int d = idx % D_;
    float rg = 0.f, rgv = 0.f;
    for (int seg = 0; seg < NSEG; seg++) {
        size_t o = ((size_t)b * NSEG + seg) * D_ + d;
        float tg = pg[o], tgv = pgv[o];
        pg[o]  = rg;
        pgv[o] = rgv;
        rg  += tg;
        rgv += tgv;
    }
}

__global__ __launch_bounds__(256) void cums_apply(
    const float* __restrict__ g, const float* __restrict__ v,
    const float* __restrict__ x,
    const float* __restrict__ pg, const float* __restrict__ pgv,
    float* __restrict__ xout)
{
    int bs  = blockIdx.x;
    int b   = bs / NSEG;
    int seg = bs % NSEG;
    int d   = blockIdx.y * 256 + threadIdx.x;
    size_t base = ((size_t)b * S_ + (size_t)seg * SEGLEN) * D_ + d;
    size_t po   = ((size_t)b * NSEG + seg) * D_ + d;

    float rg  = pg[po];
    float rgv = pgv[po];
    for (int s = 0; s < SEGLEN; s++) {
        size_t o = base + (size_t)s * D_;
        float gg = g[o];
        float vv = v[o];
        rgv += gg * vv;
        rg  += gg;
        xout[o] = x[o] + rgv / (rg + 1e-6f);
    }
}

// =================== launch ====================================================
extern "C" void kernel_launch(void* const* d_in, const int* in_sizes, int n_in,
                              void* d_out, int out_size)
{
    const float* x       = (const float*)d_in[0];
    const float* ln1_g   = (const float*)d_in[1];
    const float* ln1_b   = (const float*)d_in[2];
    const float* ln2_g   = (const float*)d_in[3];
    const float* ln2_b   = (const float*)d_in[4];
    const float* gate_w  = (const float*)d_in[5];
    const float* gate_b  = (const float*)d_in[6];
    const float* value_w = (const float*)d_in[7];
    const float* value_b = (const float*)d_in[8];
    const float* ffn_w1  = (const float*)d_in[9];
    const float* ffn_b1  = (const float*)d_in[10];
    const float* ffn_w2  = (const float*)d_in[11];
    const float* ffn_b2  = (const float*)d_in[12];
    float* out = (float*)d_out;

    float *h, *g, *v, *xn, *h2, *u, *pg, *pgv, *gwt, *vwt, *w1t, *w2t;
    cudaGetSymbolAddress((void**)&h,   sc_h);
    cudaGetSymbolAddress((void**)&g,   sc_g);
    cudaGetSymbolAddress((void**)&v,   sc_v);
    cudaGetSymbolAddress((void**)&xn,  sc_x);
    cudaGetSymbolAddress((void**)&h2,  sc_h2);
    cudaGetSymbolAddress((void**)&u,   sc_u);
    cudaGetSymbolAddress((void**)&pg,  sc_pg);
    cudaGetSymbolAddress((void**)&pgv, sc_pgv);
    cudaGetSymbolAddress((void**)&gwt, sc_gwt);
    cudaGetSymbolAddress((void**)&vwt, sc_vwt);
    cudaGetSymbolAddress((void**)&w1t, sc_w1t);
    cudaGetSymbolAddress((void**)&w2t, sc_w2t);

    cudaFuncSetAttribute(gemm_mma<EPI_SIGMOID>, cudaFuncAttributeMaxDynamicSharedMemorySize, GEMM_SMEM);
    cudaFuncSetAttribute(gemm_mma<EPI_NONE>,    cudaFuncAttributeMaxDynamicSharedMemorySize, GEMM_SMEM);
    cudaFuncSetAttribute(gemm_mma<EPI_GELU>,    cudaFuncAttributeMaxDynamicSharedMemorySize, GEMM_SMEM);
    cudaFuncSetAttribute(gemm_mma<EPI_ADD>,     cudaFuncAttributeMaxDynamicSharedMemorySize, GEMM_SMEM);

    // 0. transpose weights to [N,K] (rounds to tf32)
    transpose_kernel<<<dim3(D_/32, D_/32),   256>>>(gate_w,  gwt, D_, D_);
    transpose_kernel<<<dim3(D_/32, D_/32),   256>>>(value_w, vwt, D_, D_);
    transpose_kernel<<<dim3(4*D_/32, D_/32), 256>>>(ffn_w1,  w1t, D_, 4*D_);
    transpose_kernel<<<dim3(D_/32, 4*D_/32), 256>>>(ffn_w2,  w2t, 4*D_, D_);

    // 1. h = LN1(x)  (tf32-rounded)
    ln_kernel<<<ROWS, 256>>>(x, ln1_g, ln1_b, h);

    // 2/3. gate + value GEMMs
    dim3 gridDD(D_ / 128, ROWS / 128);
    gemm_mma<EPI_SIGMOID><<<gridDD, 256, GEMM_SMEM>>>(h, gwt, gate_b, nullptr, g, ROWS, D_, D_);
    gemm_mma<EPI_NONE>   <<<gridDD, 256, GEMM_SMEM>>>(h, vwt, value_b, nullptr, v, ROWS, D_, D_);

    // 4. memory residual
    dim3 gridCum(B_ * NSEG, D_ / 256);
    cums_partial<<<gridCum, 256>>>(g, v, pg, pgv);
    cums_scan<<<(B_ * D_) / 256, 256>>>(pg, pgv);
    cums_apply<<<gridCum, 256>>>(g, v, x, pg, pgv, xn);

    // 5. h2 = LN2(x_new)  (tf32-rounded)
    ln_kernel<<<ROWS, 256>>>(xn, ln2_g, ln2_b, h2);

    // 6. u = gelu(h2 @ W1 + b1)  (output tf32-rounded)
    dim3 gridFF1(4 * D_ / 128, ROWS / 128);
    gemm_mma<EPI_GELU><<<gridFF1, 256, GEMM_SMEM>>>(h2, w1t, ffn_b1, nullptr, u, ROWS, 4 * D_, D_);

    // 7. out = x_new + u @ W2 + b2
    gemm_mma<EPI_ADD><<<gridDD, 256, GEMM_SMEM>>>(u, w2t, ffn_b2, xn, out, ROWS, D_, 4 * D_);
}

// round 4
// speedup vs baseline: 4.4643x; 1.0965x over previous
#include <cuda_runtime.h>
#include <math.h>
#include <stdint.h>

#define B_   4
#define S_   4096
#define D_   1024
#define ROWS (B_ * S_)        // 16384
#define NSEG 32
#define SEGLEN (S_ / NSEG)    // 128

// ---------------- scratch (static device globals; no allocations) -------------
__device__ float sc_h [(size_t)ROWS * D_];
__device__ float sc_g [(size_t)ROWS * D_];
__device__ float sc_v [(size_t)ROWS * D_];
__device__ float sc_x [(size_t)ROWS * D_];
__device__ float sc_h2[(size_t)ROWS * D_];
__device__ float sc_u [(size_t)ROWS * 4 * D_];
__device__ float sc_pg [(size_t)B_ * NSEG * D_];
__device__ float sc_pgv[(size_t)B_ * NSEG * D_];
__device__ float sc_gwt[(size_t)D_ * D_];        // gate_w^T  [N,K]
__device__ float sc_vwt[(size_t)D_ * D_];        // value_w^T [N,K]
__device__ float sc_w1t[(size_t)4 * D_ * D_];    // ffn_w1^T  [4D, D]
__device__ float sc_w2t[(size_t)D_ * 4 * D_];    // ffn_w2^T  [D, 4D]

// =================== helpers ====================================================
__device__ __forceinline__ uint32_t smem_u32(const void* p) {
    uint32_t a;
    asm("{ .reg .u64 t; cvta.to.shared.u64 t, %1; cvt.u32.u64 %0, t; }"
        : "=r"(a) : "l"(p));
    return a;
}

// round-to-nearest tf32 (unbiased; applied once at producers)
__device__ __forceinline__ float tf32r(float x) {
    uint32_t u;
    asm("cvt.rna.tf32.f32 %0, %1;" : "=r"(u) : "f"(x));
    return __uint_as_float(u);
}

#define CP_COMMIT() asm volatile("cp.async.commit_group;" ::: "memory")
template <int N> __device__ __forceinline__ void cp_wait() {
    asm volatile("cp.async.wait_group %0;" :: "n"(N) : "memory");
}
__device__ __forceinline__ void cpasync16(uint32_t saddr, const void* g) {
    asm volatile("cp.async.cg.shared.global [%0], [%1], 16;"
                 :: "r"(saddr), "l"(g) : "memory");
}

__device__ __forceinline__ void mma_tf32(float* c, const uint32_t* a, const uint32_t* b) {
    asm volatile(
        "mma.sync.aligned.m16n8k8.row.col.f32.tf32.tf32.f32 "
        "{%0,%1,%2,%3}, {%4,%5,%6,%7}, {%8,%9}, {%0,%1,%2,%3};"
        : "+f"(c[0]), "+f"(c[1]), "+f"(c[2]), "+f"(c[3])
        : "r"(a[0]), "r"(a[1]), "r"(a[2]), "r"(a[3]), "r"(b[0]), "r"(b[1]));
}

// =================== mma.sync TF32 GEMM =========================================
// C[M,N] = A[M,K] @ Bt[N,K]^T (+bias, epilogue). A, Bt pre-rounded to tf32.
// 128x128 CTA tile, 128 threads (4 warps, 2x2), 64x64 warp tile, BK=32, 3 stages.
enum { EPI_NONE = 0, EPI_SIGMOID = 1, EPI_GELU = 2, EPI_ADD = 3 };

#define TILE_F   4096            // 128 rows * 32 floats (16KB), XOR-swizzled
#define STAGE_F  (2 * TILE_F)    // A + B per stage
#define NSTG     3
#define GEMM_SMEM (NSTG * STAGE_F * 4)   // 98304 bytes

template <int EPI>
__global__ __launch_bounds__(128, 2) void gemm_mma(
    const float* __restrict__ A, const float* __restrict__ Bt,
    const float* __restrict__ bias, const float* __restrict__ addsrc,
    float* __restrict__ C, int M, int N, int K)
{
    extern __shared__ float sm[];
    uint32_t smb = smem_u32(sm);

    int tid  = threadIdx.x;
    int warp = tid >> 5, lane = tid & 31;
    int g = lane >> 2, t = lane & 3;
    int wm = warp >> 1, wn = warp & 1;          // 2 x 2 warp grid, 64x64 tiles
    int row0 = blockIdx.y * 128;
    int col0 = blockIdx.x * 128;
    int KCH  = K >> 5;

    // ---- load mapping: 128 threads, each covers 8 rows (lr+16i), 16B chunk lc --
    int lr = tid >> 3;          // 0..15
    int lc = tid & 7;           // 0..7
    uint32_t st_off[8];
    #pragma unroll
    for (int i = 0; i < 8; i++) {
        int row = lr + 16 * i;
        st_off[i] = (uint32_t)(row * 128 + ((lc ^ (row & 7)) << 4));
    }
    const float* gA = A  + (size_t)(row0 + lr) * K + lc * 4;
    const float* gB = Bt + (size_t)(col0 + lr) * K + lc * 4;

    float c[4][8][4];
    #pragma unroll
    for (int i = 0; i < 4; i++)
        #pragma unroll
        for (int j = 0; j < 8; j++)
            #pragma unroll
            for (int q = 0; q < 4; q++) c[i][j][q] = 0.f;

    // prologue: stages 0,1
    #pragma unroll
    for (int s = 0; s < 2; s++) {
        uint32_t ab = smb + s * (STAGE_F * 4);
        uint32_t bb = ab + TILE_F * 4;
        #pragma unroll
        for (int i = 0; i < 8; i++) {
            cpasync16(ab + st_off[i], gA + (size_t)i * 16 * K + s * 32);
            cpasync16(bb + st_off[i], gB + (size_t)i * 16 * K + s * 32);
        }
        CP_COMMIT();
    }

    int rm0 = wm * 64 + g;      // warp row base (+16i, +8)
    int cn0 = wn * 64 + g;      // warp col base (+8j)

    for (int kc = 0; kc < KCH; kc++) {
        cp_wait<1>();           // stage kc complete (this thread's groups)
        __syncthreads();        // all threads' stage kc visible; buffer (kc+2)%3 free

        if (kc + 2 < KCH) {
            int s2 = (kc + 2) % NSTG;
            uint32_t ab = smb + s2 * (STAGE_F * 4);
            uint32_t bb = ab + TILE_F * 4;
            #pragma unroll
            for (int i = 0; i < 8; i++) {
                cpasync16(ab + st_off[i], gA + (size_t)i * 16 * K + (kc + 2) * 32);
                cpasync16(bb + st_off[i], gB + (size_t)i * 16 * K + (kc + 2) * 32);
            }
        }
        CP_COMMIT();            // always commit (keeps wait<1> accounting exact)

        const float* sA = sm + (kc % NSTG) * STAGE_F;
        const float* sB = sA + TILE_F;

        #pragma unroll
        for (int ks = 0; ks < 4; ks++) {
            int sw0 = (((2 * ks)     ^ g) << 2) + t;
            int sw1 = (((2 * ks + 1) ^ g) << 2) + t;

            uint32_t a[4][4];
            #pragma unroll
            for (int i = 0; i < 4; i++) {
                int r = rm0 + i * 16;
                a[i][0] = __float_as_uint(sA[r * 32 + sw0]);
                a[i][1] = __float_as_uint(sA[(r + 8) * 32 + sw0]);
                a[i][2] = __float_as_uint(sA[r * 32 + sw1]);
                a[i][3] = __float_as_uint(sA[(r + 8) * 32 + sw1]);
            }
            uint32_t b[8][2];
            #pragma unroll
            for (int j = 0; j < 8; j++) {
                int n = cn0 + j * 8;
                b[j][0] = __float_as_uint(sB[n * 32 + sw0]);
                b[j][1] = __float_as_uint(sB[n * 32 + sw1]);
            }
            #pragma unroll
            for (int i = 0; i < 4; i++)
                #pragma unroll
                for (int j = 0; j < 8; j++)
                    mma_tf32(c[i][j], a[i], b[j]);
        }
    }

    // ---- epilogue ---------------------------------------------------------------
    #pragma unroll
    for (int i = 0; i < 4; i++) {
        int rlo = row0 + wm * 64 + i * 16 + g;
        #pragma unroll
        for (int j = 0; j < 8; j++) {
            int col = col0 + wn * 64 + j * 8 + 2 * t;
            float2 bv = *(const float2*)(bias + col);
            float2 lo, hi;
            lo.x = c[i][j][0] + bv.x;  lo.y = c[i][j][1] + bv.y;
            hi.x = c[i][j][2] + bv.x;  hi.y = c[i][j][3] + bv.y;
            size_t olo = (size_t)rlo * N + col;
            size_t ohi = olo + (size_t)8 * N;
            if (EPI == EPI_SIGMOID) {
                lo.x = 1.f / (1.f + __expf(-lo.x)); lo.y = 1.f / (1.f + __expf(-lo.y));
                hi.x = 1.f / (1.f + __expf(-hi.x)); hi.y = 1.f / (1.f + __expf(-hi.y));
            } else if (EPI == EPI_GELU) {
                lo.x = tf32r(0.5f * lo.x * (1.f + erff(lo.x * 0.70710678118654752f)));
                lo.y = tf32r(0.5f * lo.y * (1.f + erff(lo.y * 0.70710678118654752f)));
                hi.x = tf32r(0.5f * hi.x * (1.f + erff(hi.x * 0.70710678118654752f)));
                hi.y = tf32r(0.5f * hi.y * (1.f + erff(hi.y * 0.70710678118654752f)));
            } else if (EPI == EPI_ADD) {
                float2 a0 = *(const float2*)(addsrc + olo);
                float2 a1 = *(const float2*)(addsrc + ohi);
                lo.x += a0.x; lo.y += a0.y; hi.x += a1.x; hi.y += a1.y;
            }
            *(float2*)(C + olo) = lo;
            *(float2*)(C + ohi) = hi;
        }
    }
}

// =================== transpose (rounds to tf32): in[R,C] -> out[C,R] ===========
__global__ __launch_bounds__(256) void transpose_kernel(
    const float* __restrict__ in, float* __restrict__ out, int R, int C)
{
    __shared__ float t[32][33];
    int bx = blockIdx.x * 32, by = blockIdx.y * 32;
    int tx = threadIdx.x & 31, ty = threadIdx.x >> 5;
    #pragma unroll
    for (int i = 0; i < 32; i += 8)
        t[ty + i][tx] = in[(size_t)(by + ty + i) * C + bx + tx];
    __syncthreads();
    #pragma unroll
    for (int i = 0; i < 32; i += 8)
        out[(size_t)(bx + ty + i) * R + by + tx] = tf32r(t[tx][ty + i]);
}

// =================== LayerNorm (rounds output to tf32) ========================
__global__ __launch_bounds__(256) void ln_kernel(
    const float* __restrict__ x, const float* __restrict__ gamma,
    const float* __restrict__ beta, float* __restrict__ out)
{
    int row = blockIdx.x;
    int tid = threadIdx.x;
    const float4* xr = (const float4*)(x + (size_t)row * D_);
    float4 v = xr[tid];

    float s  = v.x + v.y + v.z + v.w;
    float sq = v.x*v.x + v.y*v.y + v.z*v.z + v.w*v.w;

    __shared__ float red0[8], red1[8];
    #pragma unroll
    for (int o = 16; o > 0; o >>= 1) {
        s  += __shfl_xor_sync(0xffffffffu, s,  o);
        sq += __shfl_xor_sync(0xffffffffu, sq, o);
    }
    if ((tid & 31) == 0) { red0[tid >> 5] = s; red1[tid >> 5] = sq; }
    __syncthreads();
    if (tid < 32) {
        s  = (tid < 8) ? red0[tid] : 0.f;
        sq = (tid < 8) ? red1[tid] : 0.f;
        #pragma unroll
        for (int o = 4; o > 0; o >>= 1) {
            s  += __shfl_xor_sync(0xffffffffu, s,  o);
            sq += __shfl_xor_sync(0xffffffffu, sq, o);
        }
        if (tid == 0) {
            float mu = s * (1.0f / D_);
            float var = sq * (1.0f / D_) - mu * mu;
            red0[0] = mu;
            red1[0] = rsqrtf(var + 1e-5f);
        }
    }
    __syncthreads();
    float mu = red0[0], rstd = red1[0];

    float4 gv = ((const float4*)gamma)[tid];
    float4 bv = ((const float4*)beta)[tid];
    float4 o;
    o.x = tf32r((v.x - mu) * rstd * gv.x + bv.x);
    o.y = tf32r((v.y - mu) * rstd * gv.y + bv.y);
    o.z = tf32r((v.z - mu) * rstd * gv.z + bv.z);
    o.w = tf32r((v.w - mu) * rstd * gv.w + bv.w);
    ((float4*)(out + (size_t)row * D_))[tid] = o;
}

// =================== cumsum over sequence axis (3 passes) =====================
__global__ __launch_bounds__(256) void cums_partial(
    const float* __restrict__ g, const float* __restrict__ v,
    float* __restrict__ pg, float* __restrict__ pgv)
{
    int bs  = blockIdx.x;
    int b   = bs / NSEG;
    int seg = bs % NSEG;
    int d   = blockIdx.y * 256 + threadIdx.x;
    size_t base = ((size_t)b * S_ + (size_t)seg * SEGLEN) * D_ + d;

    float sg = 0.f, sgv = 0.f;
    #pragma unroll 4
    for (int s = 0; s < SEGLEN; s++) {
        float gg = g[base + (size_t)s * D_];
        float vv = v[base + (size_t)s * D_];
        sg  += gg;
        sgv += gg * vv;
    }
    size_t o = ((size_t)b * NSEG + seg) * D_ + d;
    pg[o]  = sg;
    pgv[o] = sgv;
}

__global__ __launch_bounds__(256) void cums_scan(
    float* __restrict__ pg, float* __restrict__ pgv)
{
    int idx = blockIdx.x * 256 + threadIdx.x;
    int b = idx / D_;
    int d = idx % D_;
    float rg = 0.f, rgv = 0.f;
    for (int seg = 0; seg < NSEG; seg++) {
        size_t o = ((size_t)b * NSEG + seg) * D_ + d;
        float tg = pg[o], tgv = pgv[o];
        pg[o]  = rg;
        pgv[o] = rgv;
        rg  += tg;
        rgv += tgv;
    }
}

__global__ __launch_bounds__(256) void cums_apply(
    const float* __restrict__ g, const float* __restrict__ v,
    const float* __restrict__ x,
    const float* __restrict__ pg, const float* __restrict__ pgv,
    float* __restrict__ xout)
{
    int bs  = blockIdx.x;
    int b   = bs / NSEG;
    int seg = bs % NSEG;
    int d   = blockIdx.y * 256 + threadIdx.x;
    size_t base = ((size_t)b * S_ + (size_t)seg * SEGLEN) * D_ + d;
    size_t po   = ((size_t)b * NSEG + seg) * D_ + d;

    float rg  = pg[po];
    float rgv = pgv[po];
    for (int s = 0; s < SEGLEN; s++) {
        size_t o = base + (size_t)s * D_;
        float gg = g[o];
        float vv = v[o];
        rgv += gg * vv;
        rg  += gg;
        xout[o] = x[o] + rgv / (rg + 1e-6f);
    }
}

// =================== launch ====================================================
extern "C" void kernel_launch(void* const* d_in, const int* in_sizes, int n_in,
                              void* d_out, int out_size)
{
    const float* x       = (const float*)d_in[0];
    const float* ln1_g   = (const float*)d_in[1];
    const float* ln1_b   = (const float*)d_in[2];
    const float* ln2_g   = (const float*)d_in[3];
    const float* ln2_b   = (const float*)d_in[4];
    const float* gate_w  = (const float*)d_in[5];
    const float* gate_b  = (const float*)d_in[6];
    const float* value_w = (const float*)d_in[7];
    const float* value_b = (const float*)d_in[8];
    const float* ffn_w1  = (const float*)d_in[9];
    const float* ffn_b1  = (const float*)d_in[10];
    const float* ffn_w2  = (const float*)d_in[11];
    const float* ffn_b2  = (const float*)d_in[12];
    float* out = (float*)d_out;

    float *h, *g, *v, *xn, *h2, *u, *pg, *pgv, *gwt, *vwt, *w1t, *w2t;
    cudaGetSymbolAddress((void**)&h,   sc_h);
    cudaGetSymbolAddress((void**)&g,   sc_g);
    cudaGetSymbolAddress((void**)&v,   sc_v);
    cudaGetSymbolAddress((void**)&xn,  sc_x);
    cudaGetSymbolAddress((void**)&h2,  sc_h2);
    cudaGetSymbolAddress((void**)&u,   sc_u);
    cudaGetSymbolAddress((void**)&pg,  sc_pg);
    cudaGetSymbolAddress((void**)&pgv, sc_pgv);
    cudaGetSymbolAddress((void**)&gwt, sc_gwt);
    cudaGetSymbolAddress((void**)&vwt, sc_vwt);
    cudaGetSymbolAddress((void**)&w1t, sc_w1t);
    cudaGetSymbolAddress((void**)&w2t, sc_w2t);

    cudaFuncSetAttribute(gemm_mma<EPI_SIGMOID>, cudaFuncAttributeMaxDynamicSharedMemorySize, GEMM_SMEM);
    cudaFuncSetAttribute(gemm_mma<EPI_NONE>,    cudaFuncAttributeMaxDynamicSharedMemorySize, GEMM_SMEM);
    cudaFuncSetAttribute(gemm_mma<EPI_GELU>,    cudaFuncAttributeMaxDynamicSharedMemorySize, GEMM_SMEM);
    cudaFuncSetAttribute(gemm_mma<EPI_ADD>,     cudaFuncAttributeMaxDynamicSharedMemorySize, GEMM_SMEM);

    // 0. transpose weights to [N,K] (rounds to tf32)
    transpose_kernel<<<dim3(D_/32, D_/32),   256>>>(gate_w,  gwt, D_, D_);
    transpose_kernel<<<dim3(D_/32, D_/32),   256>>>(value_w, vwt, D_, D_);
    transpose_kernel<<<dim3(4*D_/32, D_/32), 256>>>(ffn_w1,  w1t, D_, 4*D_);
    transpose_kernel<<<dim3(D_/32, 4*D_/32), 256>>>(ffn_w2,  w2t, 4*D_, D_);

    // 1. h = LN1(x)  (tf32-rounded)
    ln_kernel<<<ROWS, 256>>>(x, ln1_g, ln1_b, h);

    // 2/3. gate + value GEMMs
    dim3 gridDD(D_ / 128, ROWS / 128);
    gemm_mma<EPI_SIGMOID><<<gridDD, 128, GEMM_SMEM>>>(h, gwt, gate_b, nullptr, g, ROWS, D_, D_);
    gemm_mma<EPI_NONE>   <<<gridDD, 128, GEMM_SMEM>>>(h, vwt, value_b, nullptr, v, ROWS, D_, D_);

    // 4. memory residual
    dim3 gridCum(B_ * NSEG, D_ / 256);
    cums_partial<<<gridCum, 256>>>(g, v, pg, pgv);
    cums_scan<<<(B_ * D_) / 256, 256>>>(pg, pgv);
    cums_apply<<<gridCum, 256>>>(g, v, x, pg, pgv, xn);

    // 5. h2 = LN2(x_new)  (tf32-rounded)
    ln_kernel<<<ROWS, 256>>>(xn, ln2_g, ln2_b, h2);

    // 6. u = gelu(h2 @ W1 + b1)  (output tf32-rounded)
    dim3 gridFF1(4 * D_ / 128, ROWS / 128);
    gemm_mma<EPI_GELU><<<gridFF1, 128, GEMM_SMEM>>>(h2, w1t, ffn_b1, nullptr, u, ROWS, 4 * D_, D_);

    // 7. out = x_new + u @ W2 + b2
    gemm_mma<EPI_ADD><<<gridDD, 128, GEMM_SMEM>>>(u, w2t, ffn_b2, xn, out, ROWS, D_, 4 * D_);
}

// round 5
// speedup vs baseline: 7.5436x; 1.6898x over previous
#include <cuda_runtime.h>
#include <cuda_fp16.h>
#include <math.h>
#include <stdint.h>

#define B_   4
#define S_   4096
#define D_   1024
#define ROWS (B_ * S_)        // 16384
#define NSEG 32
#define SEGLEN (S_ / NSEG)    // 128

// ---------------- scratch (static device globals; no allocations) -------------
__device__ __half sc_h [(size_t)ROWS * D_];      // LN1 output (fp16)
__device__ float  sc_g [(size_t)ROWS * D_];
__device__ float  sc_v [(size_t)ROWS * D_];
__device__ float  sc_x [(size_t)ROWS * D_];
__device__ __half sc_h2[(size_t)ROWS * D_];      // LN2 output (fp16)
__device__ __half sc_u [(size_t)ROWS * 4 * D_];  // gelu out (fp16)
__device__ float  sc_pg [(size_t)B_ * NSEG * D_];
__device__ float  sc_pgv[(size_t)B_ * NSEG * D_];
__device__ __half sc_gwt[(size_t)D_ * D_];       // gate_w^T  [N,K] fp16
__device__ __half sc_vwt[(size_t)D_ * D_];       // value_w^T [N,K] fp16
__device__ __half sc_w1t[(size_t)4 * D_ * D_];   // ffn_w1^T  fp16
__device__ __half sc_w2t[(size_t)D_ * 4 * D_];   // ffn_w2^T  fp16

// =================== helpers ====================================================
__device__ __forceinline__ uint32_t smem_u32(const void* p) {
    uint32_t a;
    asm("{ .reg .u64 t; cvta.to.shared.u64 t, %1; cvt.u32.u64 %0, t; }"
        : "=r"(a) : "l"(p));
    return a;
}

#define CP_COMMIT() asm volatile("cp.async.commit_group;" ::: "memory")
template <int N> __device__ __forceinline__ void cp_wait() {
    asm volatile("cp.async.wait_group %0;" :: "n"(N) : "memory");
}
__device__ __forceinline__ void cpasync16(uint32_t saddr, const void* g) {
    asm volatile("cp.async.cg.shared.global [%0], [%1], 16;"
                 :: "r"(saddr), "l"(g) : "memory");
}

// mma.sync m16n8k16 fp16 inputs, fp32 accumulate
__device__ __forceinline__ void mma_f16(float* c, const uint32_t* a, const uint32_t* b) {
    asm volatile(
        "mma.sync.aligned.m16n8k16.row.col.f32.f16.f16.f32 "
        "{%0,%1,%2,%3}, {%4,%5,%6,%7}, {%8,%9}, {%0,%1,%2,%3};"
        : "+f"(c[0]), "+f"(c[1]), "+f"(c[2]), "+f"(c[3])
        : "r"(a[0]), "r"(a[1]), "r"(a[2]), "r"(a[3]), "r"(b[0]), "r"(b[1]));
}

__device__ __forceinline__ void store2(float* p, float x, float y) {
    float2 t; t.x = x; t.y = y; *(float2*)p = t;
}
__device__ __forceinline__ void store2(__half* p, float x, float y) {
    *(__half2*)p = __floats2half2_rn(x, y);
}

// =================== mma.sync FP16 GEMM =========================================
// C[M,N] = A[M,K] @ Bt[N,K]^T (+bias, epilogue). A, Bt fp16; accum fp32.
// 128x128 CTA tile, 128 threads (2x2 warps, 64x64 warp tile), BK=64 halfs, 3 stages.
enum { EPI_NONE = 0, EPI_SIGMOID = 1, EPI_GELU = 2, EPI_ADD = 3 };

#define TILE_B   16384                 // 128 rows * 128 bytes (64 halfs)
#define STAGE_B  (2 * TILE_B)
#define NSTG     3
#define GEMM_SMEM (NSTG * STAGE_B)     // 98304 bytes

template <int EPI, typename OutT>
__global__ __launch_bounds__(128, 2) void gemm_mma(
    const __half* __restrict__ A, const __half* __restrict__ Bt,
    const float* __restrict__ bias, const float* __restrict__ addsrc,
    OutT* __restrict__ C, int M, int N, int K)
{
    extern __shared__ char smraw[];
    uint32_t smb = smem_u32(smraw);
    const uint32_t* sm32 = (const uint32_t*)smraw;

    int tid  = threadIdx.x;
    int warp = tid >> 5, lane = tid & 31;
    int g = lane >> 2, t = lane & 3;
    int wm = warp >> 1, wn = warp & 1;          // 2 x 2 warp grid, 64x64 tiles
    int row0 = blockIdx.y * 128;
    int col0 = blockIdx.x * 128;
    int KCH  = K >> 6;                          // K chunks of 64 halfs (128B)

    // ---- load mapping: rows lr+16i, 16B chunk lc (8 chunks per 128B row) -------
    int lr = tid >> 3;          // 0..15
    int lc = tid & 7;           // 0..7
    uint32_t st_off[8];
    #pragma unroll
    for (int i = 0; i < 8; i++) {
        int row = lr + 16 * i;
        st_off[i] = (uint32_t)(row * 128 + ((lc ^ (row & 7)) << 4));
    }
    const __half* gA = A  + (size_t)(row0 + lr) * K + lc * 8;
    const __half* gB = Bt + (size_t)(col0 + lr) * K + lc * 8;

    float c[4][8][4];
    #pragma unroll
    for (int i = 0; i < 4; i++)
        #pragma unroll
        for (int j = 0; j < 8; j++)
            #pragma unroll
            for (int q = 0; q < 4; q++) c[i][j][q] = 0.f;

    // prologue: stages 0,1
    #pragma unroll
    for (int s = 0; s < 2; s++) {
        uint32_t ab = smb + s * STAGE_B;
        uint32_t bb = ab + TILE_B;
        #pragma unroll
        for (int i = 0; i < 8; i++) {
            cpasync16(ab + st_off[i], gA + (size_t)i * 16 * K + s * 64);
            cpasync16(bb + st_off[i], gB + (size_t)i * 16 * K + s * 64);
        }
        CP_COMMIT();
    }

    int rm0 = wm * 64 + g;
    int cn0 = wn * 64 + g;

    for (int kc = 0; kc < KCH; kc++) {
        cp_wait<1>();
        __syncthreads();

        if (kc + 2 < KCH) {
            int s2 = (kc + 2) % NSTG;
            uint32_t ab = smb + s2 * STAGE_B;
            uint32_t bb = ab + TILE_B;
            #pragma unroll
            for (int i = 0; i < 8; i++) {
                cpasync16(ab + st_off[i], gA + (size_t)i * 16 * K + (kc + 2) * 64);
                cpasync16(bb + st_off[i], gB + (size_t)i * 16 * K + (kc + 2) * 64);
            }
        }
        CP_COMMIT();

        // u32 view: row = 32 u32 (128B). Each u32 = f16x2 pair.
        const uint32_t* sA = sm32 + (kc % NSTG) * (STAGE_B / 4);
        const uint32_t* sB = sA + TILE_B / 4;

        #pragma unroll
        for (int ks = 0; ks < 4; ks++) {
            // chunk 2ks = k halfs [16ks..16ks+7], chunk 2ks+1 = [16ks+8..16ks+15]
            int sw0 = (((2 * ks)     ^ g) << 2) + t;   // u32 idx: chunk*4 + t  -> halfs 2t,2t+1
            int sw1 = (((2 * ks + 1) ^ g) << 2) + t;

            uint32_t a[4][4];
            #pragma unroll
            for (int i = 0; i < 4; i++) {
                int r = rm0 + i * 16;
                a[i][0] = sA[r * 32 + sw0];        // (row g,   k 16ks+2t)
                a[i][1] = sA[(r + 8) * 32 + sw0];  // (row g+8, k-lo)
                a[i][2] = sA[r * 32 + sw1];        // (row g,   k-hi)
                a[i][3] = sA[(r + 8) * 32 + sw1];  // (row g+8, k-hi)
            }
            uint32_t b[8][2];
            #pragma unroll
            for (int j = 0; j < 8; j++) {
                int n = cn0 + j * 8;
                b[j][0] = sB[n * 32 + sw0];        // (n g, k-lo pair)
                b[j][1] = sB[n * 32 + sw1];        // (n g, k-hi pair)
            }
            #pragma unroll
            for (int i = 0; i < 4; i++)
                #pragma unroll
                for (int j = 0; j < 8; j++)
                    mma_f16(c[i][j], a[i], b[j]);
        }
    }

    // ---- epilogue ---------------------------------------------------------------
    #pragma unroll
    for (int i = 0; i < 4; i++) {
        int rlo = row0 + wm * 64 + i * 16 + g;
        #pragma unroll
        for (int j = 0; j < 8; j++) {
            int col = col0 + wn * 64 + j * 8 + 2 * t;
            float2 bv = *(const float2*)(bias + col);
            float lox = c[i][j][0] + bv.x, loy = c[i][j][1] + bv.y;
            float hix = c[i][j][2] + bv.x, hiy = c[i][j][3] + bv.y;
            size_t olo = (size_t)rlo * N + col;
            size_t ohi = olo + (size_t)8 * N;
            if (EPI == EPI_SIGMOID) {
                lox = 1.f / (1.f + __expf(-lox)); loy = 1.f / (1.f + __expf(-loy));
                hix = 1.f / (1.f + __expf(-hix)); hiy = 1.f / (1.f + __expf(-hiy));
            } else if (EPI == EPI_GELU) {
                lox = 0.5f * lox * (1.f + erff(lox * 0.70710678118654752f));
                loy = 0.5f * loy * (1.f + erff(loy * 0.70710678118654752f));
                hix = 0.5f * hix * (1.f + erff(hix * 0.70710678118654752f));
                hiy = 0.5f * hiy * (1.f + erff(hiy * 0.70710678118654752f));
            } else if (EPI == EPI_ADD) {
                float2 a0 = *(const float2*)(addsrc + olo);
                float2 a1 = *(const float2*)(addsrc + ohi);
                lox += a0.x; loy += a0.y; hix += a1.x; hiy += a1.y;
            }
            store2(C + olo, lox, loy);
            store2(C + ohi, hix, hiy);
        }
    }
}

// =================== transpose (f32 -> f16): in[R,C] -> out[C,R] ===============
__global__ __launch_bounds__(256) void transpose_kernel(
    const float* __restrict__ in, __half* __restrict__ out, int R, int C)
{
    __shared__ float t[32][33];
    int bx = blockIdx.x * 32, by = blockIdx.y * 32;
    int tx = threadIdx.x & 31, ty = threadIdx.x >> 5;
    #pragma unroll
    for (int i = 0; i < 32; i += 8)
        t[ty + i][tx] = in[(size_t)(by + ty + i) * C + bx + tx];
    __syncthreads();
    #pragma unroll
    for (int i = 0; i < 32; i += 8)
        out[(size_t)(bx + ty + i) * R + by + tx] = __float2half_rn(t[tx][ty + i]);
}

// =================== LayerNorm (f32 in, f16 out) ===============================
__global__ __launch_bounds__(256) void ln_kernel(
    const float* __restrict__ x, const float* __restrict__ gamma,
    const float* __restrict__ beta, __half* __restrict__ out)
{
    int row = blockIdx.x;
    int tid = threadIdx.x;
    const float4* xr = (const float4*)(x + (size_t)row * D_);
    float4 v = xr[tid];

    float s  = v.x + v.y + v.z + v.w;
    float sq = v.x*v.x + v.y*v.y + v.z*v.z + v.w*v.w;

    __shared__ float red0[8], red1[8];
    #pragma unroll
    for (int o = 16; o > 0; o >>= 1) {
        s  += __shfl_xor_sync(0xffffffffu, s,  o);
        sq += __shfl_xor_sync(0xffffffffu, sq, o);
    }
    if ((tid & 31) == 0) { red0[tid >> 5] = s; red1[tid >> 5] = sq; }
    __syncthreads();
    if (tid < 32) {
        s  = (tid < 8) ? red0[tid] : 0.f;
        sq = (tid < 8) ? red1[tid] : 0.f;
        #pragma unroll
        for (int o = 4; o > 0; o >>= 1) {
            s  += __shfl_xor_sync(0xffffffffu, s,  o);
            sq += __shfl_xor_sync(0xffffffffu, sq, o);
        }
        if (tid == 0) {
            float mu = s * (1.0f / D_);
            float var = sq * (1.0f / D_) - mu * mu;
            red0[0] = mu;
            red1[0] = rsqrtf(var + 1e-5f);
        }
    }
    __syncthreads();
    float mu = red0[0], rstd = red1[0];

    float4 gv = ((const float4*)gamma)[tid];
    float4 bv = ((const float4*)beta)[tid];
    __half2* orow = (__half2*)(out + (size_t)row * D_);
    orow[tid * 2]     = __floats2half2_rn((v.x - mu) * rstd * gv.x + bv.x,
                                          (v.y - mu) * rstd * gv.y + bv.y);
    orow[tid * 2 + 1] = __floats2half2_rn((v.z - mu) * rstd * gv.z + bv.z,
                                          (v.w - mu) * rstd * gv.w + bv.w);
}

// =================== cumsum over sequence axis (3 passes) =====================
__global__ __launch_bounds__(256) void cums_partial(
    const float* __restrict__ g, const float* __restrict__ v,
    float* __restrict__ pg, float* __restrict__ pgv)
{
    int bs  = blockIdx.x;
    int b   = bs / NSEG;
    int seg = bs % NSEG;
    int d   = blockIdx.y * 256 + threadIdx.x;
    size_t base = ((size_t)b * S_ + (size_t)seg * SEGLEN) * D_ + d;

    float sg = 0.f, sgv = 0.f;
    #pragma unroll 4
    for (int s = 0; s < SEGLEN; s++) {
        float gg = g[base + (size_t)s * D_];
        float vv = v[base + (size_t)s * D_];
        sg  += gg;
        sgv += gg * vv;
    }
    size_t o = ((size_t)b * NSEG + seg) * D_ + d;
    pg[o]  = sg;
    pgv[o] = sgv;
}

__global__ __launch_bounds__(256) void cums_scan(
    float* __restrict__ pg, float* __restrict__ pgv)
{
    int idx = blockIdx.x * 256 + threadIdx.x;
    int b = idx / D_;
    int d = idx % D_;
    float rg = 0.f, rgv = 0.f;
    for (int seg = 0; seg < NSEG; seg++) {
        size_t o = ((size_t)b * NSEG + seg) * D_ + d;
        float tg = pg[o], tgv = pgv[o];
        pg[o]  = rg;
        pgv[o] = rgv;
        rg  += tg;
        rgv += tgv;
    }
}

__global__ __launch_bounds__(256) void cums_apply(
    const float* __restrict__ g, const float* __restrict__ v,
    const float* __restrict__ x,
    const float* __restrict__ pg, const float* __restrict__ pgv,
    float* __restrict__ xout)
{
    int bs  = blockIdx.x;
    int b   = bs / NSEG;
    int seg = bs % NSEG;
    int d   = blockIdx.y * 256 + threadIdx.x;
    size_t base = ((size_t)b * S_ + (size_t)seg * SEGLEN) * D_ + d;
    size_t po   = ((size_t)b * NSEG + seg) * D_ + d;

    float rg  = pg[po];
    float rgv = pgv[po];
    for (int s = 0; s < SEGLEN; s++) {
        size_t o = base + (size_t)s * D_;
        float gg = g[o];
        float vv = v[o];
        rgv += gg * vv;
        rg  += gg;
        xout[o] = x[o] + rgv / (rg + 1e-6f);
    }
}

// =================== launch ====================================================
extern "C" void kernel_launch(void* const* d_in, const int* in_sizes, int n_in,
                              void* d_out, int out_size)
{
    const float* x       = (const float*)d_in[0];
    const float* ln1_g   = (const float*)d_in[1];
    const float* ln1_b   = (const float*)d_in[2];
    const float* ln2_g   = (const float*)d_in[3];
    const float* ln2_b   = (const float*)d_in[4];
    const float* gate_w  = (const float*)d_in[5];
    const float* gate_b  = (const float*)d_in[6];
    const float* value_w = (const float*)d_in[7];
    const float* value_b = (const float*)d_in[8];
    const float* ffn_w1  = (const float*)d_in[9];
    const float* ffn_b1  = (const float*)d_in[10];
    const float* ffn_w2  = (const float*)d_in[11];
    const float* ffn_b2  = (const float*)d_in[12];
    float* out = (float*)d_out;

    __half *h, *h2, *u, *gwt, *vwt, *w1t, *w2t;
    float *g, *v, *xn, *pg, *pgv;
    cudaGetSymbolAddress((void**)&h,   sc_h);
    cudaGetSymbolAddress((void**)&g,   sc_g);
    cudaGetSymbolAddress((void**)&v,   sc_v);
    cudaGetSymbolAddress((void**)&xn,  sc_x);
    cudaGetSymbolAddress((void**)&h2,  sc_h2);
    cudaGetSymbolAddress((void**)&u,   sc_u);
    cudaGetSymbolAddress((void**)&pg,  sc_pg);
    cudaGetSymbolAddress((void**)&pgv, sc_pgv);
    cudaGetSymbolAddress((void**)&gwt, sc_gwt);
    cudaGetSymbolAddress((void**)&vwt, sc_vwt);
    cudaGetSymbolAddress((void**)&w1t, sc_w1t);
    cudaGetSymbolAddress((void**)&w2t, sc_w2t);

    cudaFuncSetAttribute(gemm_mma<EPI_SIGMOID, float>,  cudaFuncAttributeMaxDynamicSharedMemorySize, GEMM_SMEM);
    cudaFuncSetAttribute(gemm_mma<EPI_NONE, float>,     cudaFuncAttributeMaxDynamicSharedMemorySize, GEMM_SMEM);
    cudaFuncSetAttribute(gemm_mma<EPI_GELU, __half>,    cudaFuncAttributeMaxDynamicSharedMemorySize, GEMM_SMEM);
    cudaFuncSetAttribute(gemm_mma<EPI_ADD, float>,      cudaFuncAttributeMaxDynamicSharedMemorySize, GEMM_SMEM);

    // 0. transpose weights to [N,K] fp16
    transpose_kernel<<<dim3(D_/32, D_/32),   256>>>(gate_w,  gwt, D_, D_);
    transpose_kernel<<<dim3(D_/32, D_/32),   256>>>(value_w, vwt, D_, D_);
    transpose_kernel<<<dim3(4*D_/32, D_/32), 256>>>(ffn_w1,  w1t, D_, 4*D_);
    transpose_kernel<<<dim3(D_/32, 4*D_/32), 256>>>(ffn_w2,  w2t, 4*D_, D_);

    // 1. h = LN1(x)  (fp16)
    ln_kernel<<<ROWS, 256>>>(x, ln1_g, ln1_b, h);

    // 2/3. gate + value GEMMs
    dim3 gridDD(D_ / 128, ROWS / 128);
    gemm_mma<EPI_SIGMOID, float><<<gridDD, 128, GEMM_SMEM>>>(h, gwt, gate_b, nullptr, g, ROWS, D_, D_);
    gemm_mma<EPI_NONE, float>   <<<gridDD, 128, GEMM_SMEM>>>(h, vwt, value_b, nullptr, v, ROWS, D_, D_);

    // 4. memory residual
    dim3 gridCum(B_ * NSEG, D_ / 256);
    cums_partial<<<gridCum, 256>>>(g, v, pg, pgv);
    cums_scan<<<(B_ * D_) / 256, 256>>>(pg, pgv);
    cums_apply<<<gridCum, 256>>>(g, v, x, pg, pgv, xn);

    // 5. h2 = LN2(x_new)  (fp16)
    ln_kernel<<<ROWS, 256>>>(xn, ln2_g, ln2_b, h2);

    // 6. u = gelu(h2 @ W1 + b1)  (fp16 out)
    dim3 gridFF1(4 * D_ / 128, ROWS / 128);
    gemm_mma<EPI_GELU, __half><<<gridFF1, 128, GEMM_SMEM>>>(h2, w1t, ffn_b1, nullptr, u, ROWS, 4 * D_, D_);

    // 7. out = x_new + u @ W2 + b2
    gemm_mma<EPI_ADD, float><<<gridDD, 128, GEMM_SMEM>>>(u, w2t, ffn_b2, xn, out, ROWS, D_, 4 * D_);
}

// round 6
// speedup vs baseline: 7.6739x; 1.0173x over previous
#include <cuda_runtime.h>
#include <cuda_fp16.h>
#include <math.h>
#include <stdint.h>

#define B_   4
#define S_   4096
#define D_   1024
#define ROWS (B_ * S_)        // 16384
#define NSEG 32
#define SEGLEN (S_ / NSEG)    // 128

// ---------------- scratch (static device globals; no allocations) -------------
__device__ __half sc_h [(size_t)ROWS * D_];      // LN1 output (fp16)
__device__ float  sc_g [(size_t)ROWS * D_];
__device__ float  sc_v [(size_t)ROWS * D_];
__device__ float  sc_x [(size_t)ROWS * D_];
__device__ __half sc_h2[(size_t)ROWS * D_];      // LN2 output (fp16)
__device__ __half sc_u [(size_t)ROWS * 4 * D_];  // gelu out (fp16)
__device__ float  sc_pg [(size_t)B_ * NSEG * D_];
__device__ float  sc_pgv[(size_t)B_ * NSEG * D_];
__device__ __half sc_gwt[(size_t)D_ * D_];       // gate_w^T  [N,K] fp16
__device__ __half sc_vwt[(size_t)D_ * D_];       // value_w^T [N,K] fp16
__device__ __half sc_w1t[(size_t)4 * D_ * D_];   // ffn_w1^T  fp16
__device__ __half sc_w2t[(size_t)D_ * 4 * D_];   // ffn_w2^T  fp16

// =================== helpers ====================================================
__device__ __forceinline__ uint32_t smem_u32(const void* p) {
    uint32_t a;
    asm("{ .reg .u64 t; cvta.to.shared.u64 t, %1; cvt.u32.u64 %0, t; }"
        : "=r"(a) : "l"(p));
    return a;
}

#define CP_COMMIT() asm volatile("cp.async.commit_group;" ::: "memory")
template <int N> __device__ __forceinline__ void cp_wait() {
    asm volatile("cp.async.wait_group %0;" :: "n"(N) : "memory");
}
__device__ __forceinline__ void cpasync16(uint32_t saddr, const void* g) {
    asm volatile("cp.async.cg.shared.global [%0], [%1], 16;"
                 :: "r"(saddr), "l"(g) : "memory");
}

// mma.sync m16n8k16 fp16 inputs, fp32 accumulate
__device__ __forceinline__ void mma_f16(float* c, const uint32_t* a, const uint32_t* b) {
    asm volatile(
        "mma.sync.aligned.m16n8k16.row.col.f32.f16.f16.f32 "
        "{%0,%1,%2,%3}, {%4,%5,%6,%7}, {%8,%9}, {%0,%1,%2,%3};"
        : "+f"(c[0]), "+f"(c[1]), "+f"(c[2]), "+f"(c[3])
        : "r"(a[0]), "r"(a[1]), "r"(a[2]), "r"(a[3]), "r"(b[0]), "r"(b[1]));
}

__device__ __forceinline__ void ldm4(uint32_t* r, uint32_t a) {
    asm volatile("ldmatrix.sync.aligned.m8n8.x4.shared.b16 {%0,%1,%2,%3}, [%4];"
                 : "=r"(r[0]), "=r"(r[1]), "=r"(r[2]), "=r"(r[3]) : "r"(a));
}

__device__ __forceinline__ void store2(float* p, float x, float y) {
    float2 t; t.x = x; t.y = y; *(float2*)p = t;
}
__device__ __forceinline__ void store2(__half* p, float x, float y) {
    *(__half2*)p = __floats2half2_rn(x, y);
}

// =================== mma.sync FP16 GEMM =========================================
// C[M,N] = A[M,K] @ Bt[N,K]^T (+bias, epilogue). A, Bt fp16; accum fp32.
// 128x128 CTA tile, 128 threads (2x2 warps, 64x64 warp tile), BK=64 halfs, 3 stages.
// Fragments via ldmatrix.x4, double-buffered across k-slices.
enum { EPI_NONE = 0, EPI_SIGMOID = 1, EPI_GELU = 2, EPI_ADD = 3 };

#define TILE_B   16384                 // 128 rows * 128 bytes (64 halfs)
#define STAGE_B  (2 * TILE_B)
#define NSTG     3
#define GEMM_SMEM (NSTG * STAGE_B)     // 98304 bytes

template <int EPI, typename OutT>
__global__ __launch_bounds__(128, 2) void gemm_mma(
    const __half* __restrict__ A, const __half* __restrict__ Bt,
    const float* __restrict__ bias, const float* __restrict__ addsrc,
    OutT* __restrict__ C, int M, int N, int K)
{
    extern __shared__ char smraw[];
    uint32_t smb = smem_u32(smraw);

    int tid  = threadIdx.x;
    int warp = tid >> 5, lane = tid & 31;
    int g = lane >> 2, t = lane & 3;
    int wm = warp >> 1, wn = warp & 1;          // 2 x 2 warp grid, 64x64 tiles
    int row0 = blockIdx.y * 128;
    int col0 = blockIdx.x * 128;
    int KCH  = K >> 6;                          // K chunks of 64 halfs (128B)

    // ---- gmem->smem load mapping: rows lr+16i, 16B chunk lc -------------------
    int lr = tid >> 3;          // 0..15
    int lc = tid & 7;           // 0..7
    uint32_t st_off[8];
    #pragma unroll
    for (int i = 0; i < 8; i++) {
        int row = lr + 16 * i;
        st_off[i] = (uint32_t)(row * 128 + ((lc ^ (row & 7)) << 4));
    }
    const __half* gA = A  + (size_t)(row0 + lr) * K + lc * 8;
    const __half* gB = Bt + (size_t)(col0 + lr) * K + lc * 8;

    // ---- ldmatrix per-lane address offsets (k-slice 0; advance via ^(ks<<5)) ---
    uint32_t rxor = (uint32_t)(lane & 7) << 4;
    uint32_t aoff[4], boff[4];
    #pragma unroll
    for (int i = 0; i < 4; i++) {
        int arow = wm * 64 + i * 16 + ((lane >> 3) & 1) * 8 + (lane & 7);
        aoff[i] = (uint32_t)arow * 128 + (((uint32_t)((lane >> 4) & 1) << 4) ^ rxor);
    }
    #pragma unroll
    for (int jp = 0; jp < 4; jp++) {
        int brow = wn * 64 + jp * 16 + (((lane >> 4) & 1) << 3) + (lane & 7);
        boff[jp] = (uint32_t)brow * 128 + (((uint32_t)((lane >> 3) & 1) << 4) ^ rxor);
    }

    float c[4][8][4];
    #pragma unroll
    for (int i = 0; i < 4; i++)
        #pragma unroll
        for (int j = 0; j < 8; j++)
            #pragma unroll
            for (int q = 0; q < 4; q++) c[i][j][q] = 0.f;

    // prologue: stages 0,1
    #pragma unroll
    for (int s = 0; s < 2; s++) {
        uint32_t ab = smb + s * STAGE_B;
        uint32_t bb = ab + TILE_B;
        #pragma unroll
        for (int i = 0; i < 8; i++) {
            cpasync16(ab + st_off[i], gA + (size_t)i * 16 * K + s * 64);
            cpasync16(bb + st_off[i], gB + (size_t)i * 16 * K + s * 64);
        }
        CP_COMMIT();
    }

    for (int kc = 0; kc < KCH; kc++) {
        cp_wait<1>();
        __syncthreads();

        if (kc + 2 < KCH) {
            int s2 = (kc + 2) % NSTG;
            uint32_t ab = smb + s2 * STAGE_B;
            uint32_t bb = ab + TILE_B;
            #pragma unroll
            for (int i = 0; i < 8; i++) {
                cpasync16(ab + st_off[i], gA + (size_t)i * 16 * K + (kc + 2) * 64);
                cpasync16(bb + st_off[i], gB + (size_t)i * 16 * K + (kc + 2) * 64);
            }
        }
        CP_COMMIT();

        uint32_t sAst = smb + (kc % NSTG) * STAGE_B;
        uint32_t sBst = sAst + TILE_B;

        uint32_t af[2][4][4], bf[2][4][4];
        #pragma unroll
        for (int i = 0; i < 4; i++) ldm4(af[0][i], sAst + aoff[i]);
        #pragma unroll
        for (int jp = 0; jp < 4; jp++) ldm4(bf[0][jp], sBst + boff[jp]);

        #pragma unroll
        for (int ks = 0; ks < 4; ks++) {
            int cb = ks & 1, nb = cb ^ 1;
            if (ks < 3) {
                uint32_t kx = (uint32_t)(ks + 1) << 5;
                #pragma unroll
                for (int i = 0; i < 4; i++) ldm4(af[nb][i], sAst + (aoff[i] ^ kx));
                #pragma unroll
                for (int jp = 0; jp < 4; jp++) ldm4(bf[nb][jp], sBst + (boff[jp] ^ kx));
            }
            #pragma unroll
            for (int i = 0; i < 4; i++)
                #pragma unroll
                for (int jp = 0; jp < 4; jp++) {
                    mma_f16(c[i][2 * jp],     af[cb][i], &bf[cb][jp][0]);
                    mma_f16(c[i][2 * jp + 1], af[cb][i], &bf[cb][jp][2]);
                }
        }
    }

    // ---- epilogue ---------------------------------------------------------------
    #pragma unroll
    for (int i = 0; i < 4; i++) {
        int rlo = row0 + wm * 64 + i * 16 + g;
        #pragma unroll
        for (int j = 0; j < 8; j++) {
            int col = col0 + wn * 64 + j * 8 + 2 * t;
            float2 bv = *(const float2*)(bias + col);
            float lox = c[i][j][0] + bv.x, loy = c[i][j][1] + bv.y;
            float hix = c[i][j][2] + bv.x, hiy = c[i][j][3] + bv.y;
            size_t olo = (size_t)rlo * N + col;
            size_t ohi = olo + (size_t)8 * N;
            if (EPI == EPI_SIGMOID) {
                lox = 1.f / (1.f + __expf(-lox)); loy = 1.f / (1.f + __expf(-loy));
                hix = 1.f / (1.f + __expf(-hix)); hiy = 1.f / (1.f + __expf(-hiy));
            } else if (EPI == EPI_GELU) {
                lox = 0.5f * lox * (1.f + erff(lox * 0.70710678118654752f));
                loy = 0.5f * loy * (1.f + erff(loy * 0.70710678118654752f));
                hix = 0.5f * hix * (1.f + erff(hix * 0.70710678118654752f));
                hiy = 0.5f * hiy * (1.f + erff(hiy * 0.70710678118654752f));
            } else if (EPI == EPI_ADD) {
                float2 a0 = *(const float2*)(addsrc + olo);
                float2 a1 = *(const float2*)(addsrc + ohi);
                lox += a0.x; loy += a0.y; hix += a1.x; hiy += a1.y;
            }
            store2(C + olo, lox, loy);
            store2(C + ohi, hix, hiy);
        }
    }
}

// =================== transpose (f32 -> f16): in[R,C] -> out[C,R] ===============
__global__ __launch_bounds__(256) void transpose_kernel(
    const float* __restrict__ in, __half* __restrict__ out, int R, int C)
{
    __shared__ float t[32][33];
    int bx = blockIdx.x * 32, by = blockIdx.y * 32;
    int tx = threadIdx.x & 31, ty = threadIdx.x >> 5;
    #pragma unroll
    for (int i = 0; i < 32; i += 8)
        t[ty + i][tx] = in[(size_t)(by + ty + i) * C + bx + tx];
    __syncthreads();
    #pragma unroll
    for (int i = 0; i < 32; i += 8)
        out[(size_t)(bx + ty + i) * R + by + tx] = __float2half_rn(t[tx][ty + i]);
}

// =================== LayerNorm (f32 in, f16 out) ===============================
__global__ __launch_bounds__(256) void ln_kernel(
    const float* __restrict__ x, const float* __restrict__ gamma,
    const float* __restrict__ beta, __half* __restrict__ out)
{
    int row = blockIdx.x;
    int tid = threadIdx.x;
    const float4* xr = (const float4*)(x + (size_t)row * D_);
    float4 v = xr[tid];

    float s  = v.x + v.y + v.z + v.w;
    float sq = v.x*v.x + v.y*v.y + v.z*v.z + v.w*v.w;

    __shared__ float red0[8], red1[8];
    #pragma unroll
    for (int o = 16; o > 0; o >>= 1) {
        s  += __shfl_xor_sync(0xffffffffu, s,  o);
        sq += __shfl_xor_sync(0xffffffffu, sq, o);
    }
    if ((tid & 31) == 0) { red0[tid >> 5] = s; red1[tid >> 5] = sq; }
    __syncthreads();
    if (tid < 32) {
        s  = (tid < 8) ? red0[tid] : 0.f;
        sq = (tid < 8) ? red1[tid] : 0.f;
        #pragma unroll
        for (int o = 4; o > 0; o >>= 1) {
            s  += __shfl_xor_sync(0xffffffffu, s,  o);
            sq += __shfl_xor_sync(0xffffffffu, sq, o);
        }
        if (tid == 0) {
            float mu = s * (1.0f / D_);
            float var = sq * (1.0f / D_) - mu * mu;
            red0[0] = mu;
            red1[0] = rsqrtf(var + 1e-5f);
        }
    }
    __syncthreads();
    float mu = red0[0], rstd = red1[0];

    float4 gv = ((const float4*)gamma)[tid];
    float4 bv = ((const float4*)beta)[tid];
    __half2* orow = (__half2*)(out + (size_t)row * D_);
    orow[tid * 2]     = __floats2half2_rn((v.x - mu) * rstd * gv.x + bv.x,
                                          (v.y - mu) * rstd * gv.y + bv.y);
    orow[tid * 2 + 1] = __floats2half2_rn((v.z - mu) * rstd * gv.z + bv.z,
                                          (v.w - mu) * rstd * gv.w + bv.w);
}

// =================== cumsum over sequence axis (3 passes) =====================
__global__ __launch_bounds__(256) void cums_partial(
    const float* __restrict__ g, const float* __restrict__ v,
    float* __restrict__ pg, float* __restrict__ pgv)
{
    int bs  = blockIdx.x;
    int b   = bs / NSEG;
    int seg = bs % NSEG;
    int d   = blockIdx.y * 256 + threadIdx.x;
    size_t base = ((size_t)b * S_ + (size_t)seg * SEGLEN) * D_ + d;

    float sg = 0.f, sgv = 0.f;
    #pragma unroll 4
    for (int s = 0; s < SEGLEN; s++) {
        float gg = g[base + (size_t)s * D_];
        float vv = v[base + (size_t)s * D_];
        sg  += gg;
        sgv += gg * vv;
    }
    size_t o = ((size_t)b * NSEG + seg) * D_ + d;
    pg[o]  = sg;
    pgv[o] = sgv;
}

__global__ __launch_bounds__(256) void cums_scan(
    float* __restrict__ pg, float* __restrict__ pgv)
{
    int idx = blockIdx.x * 256 + threadIdx.x;
    int b = idx / D_;
    int d = idx % D_;
    float rg = 0.f, rgv = 0.f;
    for (int seg = 0; seg < NSEG; seg++) {
        size_t o = ((size_t)b * NSEG + seg) * D_ + d;
        float tg = pg[o], tgv = pgv[o];
        pg[o]  = rg;
        pgv[o] = rgv;
        rg  += tg;
        rgv += tgv;
    }
}

__global__ __launch_bounds__(256) void cums_apply(
    const float* __restrict__ g, const float* __restrict__ v,
    const float* __restrict__ x,
    const float* __restrict__ pg, const float* __restrict__ pgv,
    float* __restrict__ xout)
{
    int bs  = blockIdx.x;
    int b   = bs / NSEG;
    int seg = bs % NSEG;
    int d   = blockIdx.y * 256 + threadIdx.x;
    size_t base = ((size_t)b * S_ + (size_t)seg * SEGLEN) * D_ + d;
    size_t po   = ((size_t)b * NSEG + seg) * D_ + d;

    float rg  = pg[po];
    float rgv = pgv[po];
    for (int s = 0; s < SEGLEN; s++) {
        size_t o = base + (size_t)s * D_;
        float gg = g[o];
        float vv = v[o];
        rgv += gg * vv;
        rg  += gg;
        xout[o] = x[o] + rgv / (rg + 1e-6f);
    }
}

// =================== launch ====================================================
extern "C" void kernel_launch(void* const* d_in, const int* in_sizes, int n_in,
                              void* d_out, int out_size)
{
    const float* x       = (const float*)d_in[0];
    const float* ln1_g   = (const float*)d_in[1];
    const float* ln1_b   = (const float*)d_in[2];
    const float* ln2_g   = (const float*)d_in[3];
    const float* ln2_b   = (const float*)d_in[4];
    const float* gate_w  = (const float*)d_in[5];
    const float* gate_b  = (const float*)d_in[6];
    const float* value_w = (const float*)d_in[7];
    const float* value_b = (const float*)d_in[8];
    const float* ffn_w1  = (const float*)d_in[9];
    const float* ffn_b1  = (const float*)d_in[10];
    const float* ffn_w2  = (const float*)d_in[11];
    const float* ffn_b2  = (const float*)d_in[12];
    float* out = (float*)d_out;

    __half *h, *h2, *u, *gwt, *vwt, *w1t, *w2t;
    float *g, *v, *xn, *pg, *pgv;
    cudaGetSymbolAddress((void**)&h,   sc_h);
    cudaGetSymbolAddress((void**)&g,   sc_g);
    cudaGetSymbolAddress((void**)&v,   sc_v);
    cudaGetSymbolAddress((void**)&xn,  sc_x);
    cudaGetSymbolAddress((void**)&h2,  sc_h2);
    cudaGetSymbolAddress((void**)&u,   sc_u);
    cudaGetSymbolAddress((void**)&pg,  sc_pg);
    cudaGetSymbolAddress((void**)&pgv, sc_pgv);
    cudaGetSymbolAddress((void**)&gwt, sc_gwt);
    cudaGetSymbolAddress((void**)&vwt, sc_vwt);
    cudaGetSymbolAddress((void**)&w1t, sc_w1t);
    cudaGetSymbolAddress((void**)&w2t, sc_w2t);

    cudaFuncSetAttribute(gemm_mma<EPI_SIGMOID, float>,  cudaFuncAttributeMaxDynamicSharedMemorySize, GEMM_SMEM);
    cudaFuncSetAttribute(gemm_mma<EPI_NONE, float>,     cudaFuncAttributeMaxDynamicSharedMemorySize, GEMM_SMEM);
    cudaFuncSetAttribute(gemm_mma<EPI_GELU, __half>,    cudaFuncAttributeMaxDynamicSharedMemorySize, GEMM_SMEM);
    cudaFuncSetAttribute(gemm_mma<EPI_ADD, float>,      cudaFuncAttributeMaxDynamicSharedMemorySize, GEMM_SMEM);

    // 0. transpose weights to [N,K] fp16
    transpose_kernel<<<dim3(D_/32, D_/32),   256>>>(gate_w,  gwt, D_, D_);
    transpose_kernel<<<dim3(D_/32, D_/32),   256>>>(value_w, vwt, D_, D_);
    transpose_kernel<<<dim3(4*D_/32, D_/32), 256>>>(ffn_w1,  w1t, D_, 4*D_);
    transpose_kernel<<<dim3(D_/32, 4*D_/32), 256>>>(ffn_w2,  w2t, 4*D_, D_);

    // 1. h = LN1(x)  (fp16)
    ln_kernel<<<ROWS, 256>>>(x, ln1_g, ln1_b, h);

    // 2/3. gate + value GEMMs
    dim3 gridDD(D_ / 128, ROWS / 128);
    gemm_mma<EPI_SIGMOID, float><<<gridDD, 128, GEMM_SMEM>>>(h, gwt, gate_b, nullptr, g, ROWS, D_, D_);
    gemm_mma<EPI_NONE, float>   <<<gridDD, 128, GEMM_SMEM>>>(h, vwt, value_b, nullptr, v, ROWS, D_, D_);

    // 4. memory residual
    dim3 gridCum(B_ * NSEG, D_ / 256);
    cums_partial<<<gridCum, 256>>>(g, v, pg, pgv);
    cums_scan<<<(B_ * D_) / 256, 256>>>(pg, pgv);
    cums_apply<<<gridCum, 256>>>(g, v, x, pg, pgv, xn);

    // 5. h2 = LN2(x_new)  (fp16)
    ln_kernel<<<ROWS, 256>>>(xn, ln2_g, ln2_b, h2);

    // 6. u = gelu(h2 @ W1 + b1)  (fp16 out)
    dim3 gridFF1(4 * D_ / 128, ROWS / 128);
    gemm_mma<EPI_GELU, __half><<<gridFF1, 128, GEMM_SMEM>>>(h2, w1t, ffn_b1, nullptr, u, ROWS, 4 * D_, D_);

    // 7. out = x_new + u @ W2 + b2
    gemm_mma<EPI_ADD, float><<<gridDD, 128, GEMM_SMEM>>>(u, w2t, ffn_b2, xn, out, ROWS, D_, 4 * D_);
}